// round 4
// baseline (speedup 1.0000x reference)
#include <cuda_runtime.h>

#define NN 50000
#define D 128
#define EE 800000

// Scratch (device globals: allocation-free per harness rules)
__device__ __align__(16) float g_h[NN * D];     // GEMM output (both layers)
__device__ __align__(16) float g_x1[NN * D];    // layer-1 activations
__device__ float g_deg[NN];
__device__ float g_dinv[NN];
__device__ int   g_cnt[NN];                     // per-dst edge count
__device__ int   g_cur[NN];                     // scatter cursor
__device__ int   g_off[NN + 1];                 // CSR offsets
__device__ int   g_csr_src[EE];                 // src node per CSR slot
__device__ float g_csr_coef[EE];                // norm coefficient per CSR slot
__device__ int   g_detect;                      // 0 => int64 edge_index, else int32

// Edge-index loader: dtype decided at runtime from g_detect.
__device__ __forceinline__ int ld_edge(const void* ei, long long pos, int is32) {
    if (is32) return ((const int*)ei)[pos];
    return (int)((const long long*)ei)[pos];
}

// ---------------------------------------------------------------------------
// Init: deg = 1 (self loop), counters = 0, detect = 0
// ---------------------------------------------------------------------------
__global__ void init_kernel(int n) {
    int i = blockIdx.x * blockDim.x + threadIdx.x;
    if (i < n) {
        g_deg[i] = 1.0f;
        g_cnt[i] = 0;
        g_cur[i] = 0;
    }
    if (i == 0) g_detect = 0;
}

// Probe edge_index layout: for int64 values < 2^31 every odd 32-bit word is 0.
__global__ void detect_kernel(const int* __restrict__ ei32, int E) {
    int acc = 0;
    for (int i = threadIdx.x; i < 2048 && i < E; i += blockDim.x)
        acc |= ei32[2 * i + 1];
    // warp+block reduce via atomic (tiny kernel, cost irrelevant)
    if (acc) atomicOr(&g_detect, 1);
}

// Degree accumulate + dst histogram (one pass over edges)
__global__ void deg_hist_kernel(const void* __restrict__ ei,
                                const float* __restrict__ ew, int E, int n) {
    int e = blockIdx.x * blockDim.x + threadIdx.x;
    if (e < E) {
        int is32 = g_detect;
        int d = ld_edge(ei, (long long)E + e, is32);
        if ((unsigned)d >= (unsigned)n) return;  // defensive
        atomicAdd(&g_deg[d], ew[e]);
        atomicAdd(&g_cnt[d], 1);
    }
}

__global__ void dinv_kernel(int n) {
    int i = blockIdx.x * blockDim.x + threadIdx.x;
    if (i < n) {
        float dg = g_deg[i];
        g_dinv[i] = (dg > 0.0f) ? rsqrtf(dg) : 0.0f;
    }
}

// ---------------------------------------------------------------------------
// Single-block exclusive scan of g_cnt -> g_off
// ---------------------------------------------------------------------------
__global__ void scan_kernel(int n, int E) {
    __shared__ int s[1024];
    int t = threadIdx.x;
    int chunk = (n + 1023) >> 10;
    int start = t * chunk;
    int stop = min(start + chunk, n);

    int sum = 0;
    for (int i = start; i < stop; i++) sum += g_cnt[i];
    s[t] = sum;
    __syncthreads();

    for (int off = 1; off < 1024; off <<= 1) {
        int v = 0;
        if (t >= off) v = s[t - off];
        __syncthreads();
        if (t >= off) s[t] += v;
        __syncthreads();
    }

    int run = (t == 0) ? 0 : s[t - 1];
    for (int i = start; i < stop; i++) {
        g_off[i] = run;
        run += g_cnt[i];
    }
    if (t == 1023) g_off[n] = s[1023];
}

// ---------------------------------------------------------------------------
// Counting-sort scatter: place (src, coef) into CSR slots grouped by dst.
// coef = dinv[src] * ew * dinv[dst] (same for both layers).
// ---------------------------------------------------------------------------
__global__ void scatter_kernel(const void* __restrict__ ei,
                               const float* __restrict__ ew, int E, int n) {
    int e = blockIdx.x * blockDim.x + threadIdx.x;
    if (e < E) {
        int is32 = g_detect;
        int s = ld_edge(ei, e, is32);
        int d = ld_edge(ei, (long long)E + e, is32);
        if ((unsigned)s >= (unsigned)n || (unsigned)d >= (unsigned)n) return;
        int pos = g_off[d] + atomicAdd(&g_cur[d], 1);
        g_csr_src[pos] = s;
        g_csr_coef[pos] = g_dinv[s] * ew[e] * g_dinv[d];
    }
}

// ---------------------------------------------------------------------------
// GEMM: g_h = X * W  (X: [n,128], W: [128,128])
// Block = 128 threads, 16 nodes per block. tx = lane owns dims [4tx,4tx+4).
// ---------------------------------------------------------------------------
__global__ void gemm_kernel(const float* __restrict__ X,
                            const float* __restrict__ W, int n) {
    __shared__ float xs[16][D];
    int node0 = blockIdx.x * 16;
    int t = threadIdx.x;

    for (int i = t; i < 16 * (D / 4); i += 128) {
        int r = i >> 5;
        int c = i & 31;
        if (node0 + r < n)
            ((float4*)&xs[r][0])[c] =
                __ldg((const float4*)(X + (size_t)(node0 + r) * D) + c);
    }
    __syncthreads();

    int tx = t & 31;
    int tg = t >> 5;

    float4 acc[4];
#pragma unroll
    for (int i = 0; i < 4; i++) acc[i] = make_float4(0.f, 0.f, 0.f, 0.f);

#pragma unroll 4
    for (int k = 0; k < D; k++) {
        float4 w = __ldg((const float4*)(W + (size_t)k * D) + tx);
#pragma unroll
        for (int i = 0; i < 4; i++) {
            float xv = xs[tg * 4 + i][k];
            acc[i].x += xv * w.x;
            acc[i].y += xv * w.y;
            acc[i].z += xv * w.z;
            acc[i].w += xv * w.w;
        }
    }

#pragma unroll
    for (int i = 0; i < 4; i++) {
        int node = node0 + tg * 4 + i;
        if (node < n)
            ((float4*)(g_h + (size_t)node * D))[tx] = acc[i];
    }
}

// Layer-2 GEMM reads g_x1 directly
__global__ void gemm2_kernel(const float* __restrict__ W, int n) {
    __shared__ float xs[16][D];
    int node0 = blockIdx.x * 16;
    int t = threadIdx.x;

    for (int i = t; i < 16 * (D / 4); i += 128) {
        int r = i >> 5;
        int c = i & 31;
        if (node0 + r < n)
            ((float4*)&xs[r][0])[c] =
                ((const float4*)(g_x1 + (size_t)(node0 + r) * D))[c];
    }
    __syncthreads();

    int tx = t & 31;
    int tg = t >> 5;

    float4 acc[4];
#pragma unroll
    for (int i = 0; i < 4; i++) acc[i] = make_float4(0.f, 0.f, 0.f, 0.f);

#pragma unroll 4
    for (int k = 0; k < D; k++) {
        float4 w = __ldg((const float4*)(W + (size_t)k * D) + tx);
#pragma unroll
        for (int i = 0; i < 4; i++) {
            float xv = xs[tg * 4 + i][k];
            acc[i].x += xv * w.x;
            acc[i].y += xv * w.y;
            acc[i].z += xv * w.z;
            acc[i].w += xv * w.w;
        }
    }

#pragma unroll
    for (int i = 0; i < 4; i++) {
        int node = node0 + tg * 4 + i;
        if (node < n)
            ((float4*)(g_h + (size_t)node * D))[tx] = acc[i];
    }
}

// ---------------------------------------------------------------------------
// Pull aggregation, layer 1: warp per dst node, lane owns 4 dims.
// x1 = relu(sum_in coef*h[src] + dinv^2*h[node] + b1)
// ---------------------------------------------------------------------------
__global__ void agg1_kernel(const float* __restrict__ b, int n) {
    int node = blockIdx.x * 8 + (threadIdx.x >> 5);
    int lane = threadIdx.x & 31;
    if (node >= n) return;

    int beg = g_off[node];
    int end = g_off[node + 1];

    float4 acc = make_float4(0.f, 0.f, 0.f, 0.f);
    for (int j = beg; j < end; j++) {
        int s = __ldg(&g_csr_src[j]);
        float c = __ldg(&g_csr_coef[j]);
        float4 h = __ldg((const float4*)g_h + (size_t)s * 32 + lane);
        acc.x += c * h.x;
        acc.y += c * h.y;
        acc.z += c * h.z;
        acc.w += c * h.w;
    }

    float sl = g_dinv[node];
    sl = sl * sl;
    float4 hs = ((const float4*)g_h)[(size_t)node * 32 + lane];
    float4 bias = __ldg((const float4*)b + lane);
    float4 v;
    v.x = fmaxf(acc.x + sl * hs.x + bias.x, 0.f);
    v.y = fmaxf(acc.y + sl * hs.y + bias.y, 0.f);
    v.z = fmaxf(acc.z + sl * hs.z + bias.z, 0.f);
    v.w = fmaxf(acc.w + sl * hs.w + bias.w, 0.f);
    ((float4*)g_x1)[(size_t)node * 32 + lane] = v;
}

// ---------------------------------------------------------------------------
// Pull aggregation, layer 2 + interleaved output [n, 128, 2]
// ---------------------------------------------------------------------------
__global__ void agg2_kernel(const float* __restrict__ b,
                            float* __restrict__ out, int n) {
    int node = blockIdx.x * 8 + (threadIdx.x >> 5);
    int lane = threadIdx.x & 31;
    if (node >= n) return;

    int beg = g_off[node];
    int end = g_off[node + 1];

    float4 acc = make_float4(0.f, 0.f, 0.f, 0.f);
    for (int j = beg; j < end; j++) {
        int s = __ldg(&g_csr_src[j]);
        float c = __ldg(&g_csr_coef[j]);
        float4 h = __ldg((const float4*)g_h + (size_t)s * 32 + lane);
        acc.x += c * h.x;
        acc.y += c * h.y;
        acc.z += c * h.z;
        acc.w += c * h.w;
    }

    float sl = g_dinv[node];
    sl = sl * sl;
    float4 hs = ((const float4*)g_h)[(size_t)node * 32 + lane];
    float4 bias = __ldg((const float4*)b + lane);
    float4 v2;
    v2.x = fmaxf(acc.x + sl * hs.x + bias.x, 0.f);
    v2.y = fmaxf(acc.y + sl * hs.y + bias.y, 0.f);
    v2.z = fmaxf(acc.z + sl * hs.z + bias.z, 0.f);
    v2.w = fmaxf(acc.w + sl * hs.w + bias.w, 0.f);

    float4 v1 = ((const float4*)g_x1)[(size_t)node * 32 + lane];
    float4 lo = make_float4(v1.x, v2.x, v1.y, v2.y);
    float4 hi = make_float4(v1.z, v2.z, v1.w, v2.w);
    size_t o = (size_t)node * 64 + (size_t)lane * 2;
    ((float4*)out)[o] = lo;
    ((float4*)out)[o + 1] = hi;
}

// ---------------------------------------------------------------------------
extern "C" void kernel_launch(void* const* d_in, const int* in_sizes, int n_in,
                              void* d_out, int out_size) {
    const float* x = (const float*)d_in[0];
    const void* ei = d_in[1];                 // int32 or int64; probed on device
    const float* ew = (const float*)d_in[2];
    const float* W1 = (const float*)d_in[3];
    const float* b1 = (const float*)d_in[4];
    const float* W2 = (const float*)d_in[5];
    const float* b2 = (const float*)d_in[6];
    float* out = (float*)d_out;

    int n = in_sizes[0] / D;   // 50000
    int E = in_sizes[2];       // 800000

    int tb = 256;
    int nodeBlocks = (n + tb - 1) / tb;
    int edgeBlocks = (E + tb - 1) / tb;
    int gemmBlocks = (n + 15) / 16;
    int aggBlocks = (n + 7) / 8;

    // Graph preprocessing (shared by both layers)
    init_kernel<<<nodeBlocks, tb>>>(n);
    detect_kernel<<<1, 256>>>((const int*)ei, E);
    deg_hist_kernel<<<edgeBlocks, tb>>>(ei, ew, E, n);
    dinv_kernel<<<nodeBlocks, tb>>>(n);
    scan_kernel<<<1, 1024>>>(n, E);
    scatter_kernel<<<edgeBlocks, tb>>>(ei, ew, E, n);

    // ---- Layer 1 ----
    gemm_kernel<<<gemmBlocks, 128>>>(x, W1, n);
    agg1_kernel<<<aggBlocks, tb>>>(b1, n);

    // ---- Layer 2 ----
    gemm2_kernel<<<gemmBlocks, 128>>>(W2, n);
    agg2_kernel<<<aggBlocks, tb>>>(b2, out, n);
}

// round 5
// speedup vs baseline: 1.1110x; 1.1110x over previous
#include <cuda_runtime.h>

#define NN 50000
#define D 128
#define EE 800000

typedef unsigned long long ull;

// Scratch (device globals: allocation-free per harness rules)
__device__ __align__(16) float g_h[NN * D];     // GEMM output (both layers)
__device__ __align__(16) float g_x1[NN * D];    // layer-1 activations
__device__ float g_deg[NN];
__device__ float g_dinv[NN];
__device__ int   g_cnt[NN];
__device__ int   g_cur[NN];
__device__ int   g_off[NN + 1];
__device__ int   g_csr_src[EE];
__device__ float g_csr_coef[EE];
__device__ int   g_detect;                      // 0 => int64 edge_index, else int32

// ---- packed f32x2 helpers (sm_103a) ---------------------------------------
__device__ __forceinline__ ull pk2(float a) {
    ull r; asm("mov.b64 %0, {%1, %1};" : "=l"(r) : "f"(a)); return r;
}
__device__ __forceinline__ void fma2(ull& d, ull a, ull b) {
    asm("fma.rn.f32x2 %0, %1, %2, %0;" : "+l"(d) : "l"(a), "l"(b));
}
__device__ __forceinline__ float2 unpk(ull a) {
    float2 r; asm("mov.b64 {%0, %1}, %2;" : "=f"(r.x), "=f"(r.y) : "l"(a)); return r;
}

__device__ __forceinline__ int ld_edge(const void* ei, long long pos, int is32) {
    if (is32) return ((const int*)ei)[pos];
    return (int)((const long long*)ei)[pos];
}

// ---------------------------------------------------------------------------
// Preprocessing
// ---------------------------------------------------------------------------
__global__ void init_kernel(int n) {
    int i = blockIdx.x * blockDim.x + threadIdx.x;
    if (i < n) {
        g_deg[i] = 1.0f;
        g_cnt[i] = 0;
        g_cur[i] = 0;
    }
    if (i == 0) g_detect = 0;
}

__global__ void detect_kernel(const int* __restrict__ ei32, int E) {
    int acc = 0;
    for (int i = threadIdx.x; i < 2048 && i < E; i += blockDim.x)
        acc |= ei32[2 * i + 1];
    if (acc) atomicOr(&g_detect, 1);
}

__global__ void deg_hist_kernel(const void* __restrict__ ei,
                                const float* __restrict__ ew, int E, int n) {
    int e = blockIdx.x * blockDim.x + threadIdx.x;
    if (e < E) {
        int is32 = g_detect;
        int d = ld_edge(ei, (long long)E + e, is32);
        if ((unsigned)d >= (unsigned)n) return;
        atomicAdd(&g_deg[d], ew[e]);
        atomicAdd(&g_cnt[d], 1);
    }
}

__global__ void dinv_kernel(int n) {
    int i = blockIdx.x * blockDim.x + threadIdx.x;
    if (i < n) {
        float dg = g_deg[i];
        g_dinv[i] = (dg > 0.0f) ? rsqrtf(dg) : 0.0f;
    }
}

__global__ void scan_kernel(int n, int E) {
    __shared__ int s[1024];
    int t = threadIdx.x;
    int chunk = (n + 1023) >> 10;
    int start = t * chunk;
    int stop = min(start + chunk, n);

    int sum = 0;
    for (int i = start; i < stop; i++) sum += g_cnt[i];
    s[t] = sum;
    __syncthreads();

    for (int off = 1; off < 1024; off <<= 1) {
        int v = 0;
        if (t >= off) v = s[t - off];
        __syncthreads();
        if (t >= off) s[t] += v;
        __syncthreads();
    }

    int run = (t == 0) ? 0 : s[t - 1];
    for (int i = start; i < stop; i++) {
        g_off[i] = run;
        run += g_cnt[i];
    }
    if (t == 1023) g_off[n] = s[1023];
}

__global__ void scatter_kernel(const void* __restrict__ ei,
                               const float* __restrict__ ew, int E, int n) {
    int e = blockIdx.x * blockDim.x + threadIdx.x;
    if (e < E) {
        int is32 = g_detect;
        int s = ld_edge(ei, e, is32);
        int d = ld_edge(ei, (long long)E + e, is32);
        if ((unsigned)s >= (unsigned)n || (unsigned)d >= (unsigned)n) return;
        int pos = g_off[d] + atomicAdd(&g_cur[d], 1);
        g_csr_src[pos] = s;
        g_csr_coef[pos] = g_dinv[s] * ew[e] * g_dinv[d];
    }
}

// ---------------------------------------------------------------------------
// GEMM: g_h = X * W  (X: [n,128], W: [128,128]) using packed f32x2 FMA.
// Block = 128 threads, 16 nodes. Transposed x-tile; W read as f32x2 pairs.
// ---------------------------------------------------------------------------
__global__ void gemm_kernel(const float* __restrict__ X,
                            const float* __restrict__ W, int n) {
    __shared__ float xsT[D][20];  // [k][node], padded stride for fill conflicts
    int node0 = blockIdx.x * 16;
    int t = threadIdx.x;  // 128 threads; t = feature column k for the fill

#pragma unroll
    for (int r = 0; r < 16; r++) {
        float v = (node0 + r < n) ? __ldg(X + (size_t)(node0 + r) * D + t) : 0.f;
        xsT[t][r] = v;
    }
    __syncthreads();

    int tx = t & 31;   // owns dims [4tx, 4tx+4)
    int tg = t >> 5;   // owns nodes [4tg, 4tg+4)

    ull acc[4][2];
#pragma unroll
    for (int i = 0; i < 4; i++) { acc[i][0] = 0ull; acc[i][1] = 0ull; }

#pragma unroll 2
    for (int k = 0; k < D; k++) {
        longlong2 w2 = __ldg((const longlong2*)W + (size_t)k * 32 + tx);
        float4 xv = *(const float4*)&xsT[k][tg * 4];  // warp broadcast
        ull wlo = (ull)w2.x, whi = (ull)w2.y;
        ull xp;
        xp = pk2(xv.x); fma2(acc[0][0], xp, wlo); fma2(acc[0][1], xp, whi);
        xp = pk2(xv.y); fma2(acc[1][0], xp, wlo); fma2(acc[1][1], xp, whi);
        xp = pk2(xv.z); fma2(acc[2][0], xp, wlo); fma2(acc[2][1], xp, whi);
        xp = pk2(xv.w); fma2(acc[3][0], xp, wlo); fma2(acc[3][1], xp, whi);
    }

#pragma unroll
    for (int i = 0; i < 4; i++) {
        int node = node0 + tg * 4 + i;
        if (node < n) {
            ulonglong2 v; v.x = acc[i][0]; v.y = acc[i][1];
            ((ulonglong2*)(g_h + (size_t)node * D))[tx] = v;
        }
    }
}

// ---------------------------------------------------------------------------
// Pull aggregation: warp per dst node, lane owns 4 dims (2 f32x2 pairs).
// ---------------------------------------------------------------------------
__device__ __forceinline__ void agg_core(int node, int lane, ull& a0, ull& a1) {
    int beg = g_off[node];
    int end = g_off[node + 1];
    const ulonglong2* hv = (const ulonglong2*)g_h;

    int j = beg;
    for (; j + 1 < end; j += 2) {
        int s0 = __ldg(&g_csr_src[j]);
        int s1 = __ldg(&g_csr_src[j + 1]);
        float c0 = __ldg(&g_csr_coef[j]);
        float c1 = __ldg(&g_csr_coef[j + 1]);
        ulonglong2 h0 = __ldg(hv + (size_t)s0 * 32 + lane);
        ulonglong2 h1 = __ldg(hv + (size_t)s1 * 32 + lane);
        ull cp0 = pk2(c0), cp1 = pk2(c1);
        fma2(a0, cp0, h0.x); fma2(a1, cp0, h0.y);
        fma2(a0, cp1, h1.x); fma2(a1, cp1, h1.y);
    }
    if (j < end) {
        int s0 = __ldg(&g_csr_src[j]);
        float c0 = __ldg(&g_csr_coef[j]);
        ulonglong2 h0 = __ldg(hv + (size_t)s0 * 32 + lane);
        ull cp0 = pk2(c0);
        fma2(a0, cp0, h0.x); fma2(a1, cp0, h0.y);
    }

    // self-loop: + dinv^2 * h[node]
    float sl = g_dinv[node];
    ull slp = pk2(sl * sl);
    ulonglong2 hs = hv[(size_t)node * 32 + lane];
    fma2(a0, slp, hs.x); fma2(a1, slp, hs.y);
}

__global__ void agg1_kernel(const float* __restrict__ b, int n) {
    int node = blockIdx.x * 8 + (threadIdx.x >> 5);
    int lane = threadIdx.x & 31;
    if (node >= n) return;

    ull a0 = 0ull, a1 = 0ull;
    agg_core(node, lane, a0, a1);

    float2 p0 = unpk(a0), p1 = unpk(a1);
    float4 bias = __ldg((const float4*)b + lane);
    float4 v;
    v.x = fmaxf(p0.x + bias.x, 0.f);
    v.y = fmaxf(p0.y + bias.y, 0.f);
    v.z = fmaxf(p1.x + bias.z, 0.f);
    v.w = fmaxf(p1.y + bias.w, 0.f);
    ((float4*)g_x1)[(size_t)node * 32 + lane] = v;
}

__global__ void agg2_kernel(const float* __restrict__ b,
                            float* __restrict__ out, int n) {
    int node = blockIdx.x * 8 + (threadIdx.x >> 5);
    int lane = threadIdx.x & 31;
    if (node >= n) return;

    ull a0 = 0ull, a1 = 0ull;
    agg_core(node, lane, a0, a1);

    float2 p0 = unpk(a0), p1 = unpk(a1);
    float4 bias = __ldg((const float4*)b + lane);
    float4 v2;
    v2.x = fmaxf(p0.x + bias.x, 0.f);
    v2.y = fmaxf(p0.y + bias.y, 0.f);
    v2.z = fmaxf(p1.x + bias.z, 0.f);
    v2.w = fmaxf(p1.y + bias.w, 0.f);

    float4 v1 = ((const float4*)g_x1)[(size_t)node * 32 + lane];
    float4 lo = make_float4(v1.x, v2.x, v1.y, v2.y);
    float4 hi = make_float4(v1.z, v2.z, v1.w, v2.w);
    size_t o = (size_t)node * 64 + (size_t)lane * 2;
    ((float4*)out)[o] = lo;
    ((float4*)out)[o + 1] = hi;
}

// ---------------------------------------------------------------------------
extern "C" void kernel_launch(void* const* d_in, const int* in_sizes, int n_in,
                              void* d_out, int out_size) {
    const float* x = (const float*)d_in[0];
    const void* ei = d_in[1];
    const float* ew = (const float*)d_in[2];
    const float* W1 = (const float*)d_in[3];
    const float* b1 = (const float*)d_in[4];
    const float* W2 = (const float*)d_in[5];
    const float* b2 = (const float*)d_in[6];
    float* out = (float*)d_out;

    int n = in_sizes[0] / D;   // 50000
    int E = in_sizes[2];       // 800000

    // One-time host objects (created on the uncaptured correctness call)
    static cudaStream_t s2 = nullptr;
    static cudaEvent_t evRoot = nullptr, evPrep = nullptr;
    static const float* x1_ptr = nullptr;
    if (!s2) {
        cudaStreamCreateWithFlags(&s2, cudaStreamNonBlocking);
        cudaEventCreateWithFlags(&evRoot, cudaEventDisableTiming);
        cudaEventCreateWithFlags(&evPrep, cudaEventDisableTiming);
        void* p = nullptr;
        cudaGetSymbolAddress(&p, g_x1);
        x1_ptr = (const float*)p;
    }

    int tb = 256;
    int nodeBlocks = (n + tb - 1) / tb;
    int edgeBlocks = (E + tb - 1) / tb;
    int gemmBlocks = (n + 15) / 16;
    int aggBlocks = (n + 7) / 8;

    // Fork: CSR preprocessing on s2, concurrent with GEMM1 on default stream.
    cudaEventRecord(evRoot, 0);
    cudaStreamWaitEvent(s2, evRoot, 0);

    init_kernel<<<nodeBlocks, tb, 0, s2>>>(n);
    detect_kernel<<<1, 256, 0, s2>>>((const int*)ei, E);
    deg_hist_kernel<<<edgeBlocks, tb, 0, s2>>>(ei, ew, E, n);
    dinv_kernel<<<nodeBlocks, tb, 0, s2>>>(n);
    scan_kernel<<<1, 1024, 0, s2>>>(n, E);
    scatter_kernel<<<edgeBlocks, tb, 0, s2>>>(ei, ew, E, n);
    cudaEventRecord(evPrep, s2);

    gemm_kernel<<<gemmBlocks, 128>>>(x, W1, n);

    // Join: aggregation needs both CSR and GEMM1 output.
    cudaStreamWaitEvent(0, evPrep, 0);

    agg1_kernel<<<aggBlocks, tb>>>(b1, n);
    gemm_kernel<<<gemmBlocks, 128>>>(x1_ptr, W2, n);
    agg2_kernel<<<aggBlocks, tb>>>(b2, out, n);
}